// round 16
// baseline (speedup 1.0000x reference)
#include <cuda_runtime.h>
#include <cuda_bf16.h>

// D_MODEL = 2048, QUAT_DIM = 512, B*T = 16384
// Inputs: x [B,T,2048] f32, q_left [4,512] f32, q_right [4,512] f32, gate [512] f32
// Output: [B,T,2048] f32
//
// gate broadcasts uniformly over the FFT axis => ifft(fft(x)*g).real == g*x.
// Both Hamilton products are linear in x => fused per-feature 4x4 matrix M[d].
//
// R14: R12's pair-burst body (compiled to exactly 64 regs) launched at
// 592 blocks = 148 SMs x 4 resident (launch_bounds min-blocks=4 pins regs<=64).
// Grid was the occupancy limiter in all prior persistent variants (444 = 3/SM).

#define QD 512
#define NBT (4 * 4096)        // 16384 rows
#define THREADS 256
#define NBLK 592              // 148 SMs x 4 resident
#define STRIDE (NBLK * 2048)  // floats between a block's consecutive rows
// 16384 = 592*27 + 400 -> blocks 0..399: 28 rows (14 pairs),
//                         blocks 400..591: 27 rows (13 pairs + 1 tail row).

__device__ __forceinline__ float2 f2_fma(float2 a, float2 b, float2 c) {
    return make_float2(fmaf(a.x, b.x, c.x), fmaf(a.y, b.y, c.y));
}
__device__ __forceinline__ float2 f2_mul(float2 a, float2 b) {
    return make_float2(a.x * b.x, a.y * b.y);
}

__global__ void __launch_bounds__(THREADS, 4)
evolve_pair4_kernel(const float* __restrict__ x,
                    const float* __restrict__ ql,
                    const float* __restrict__ qr,
                    const float* __restrict__ gate,
                    float* __restrict__ out) {
    const int d2 = threadIdx.x * 2;        // feature pair
    const int bid = blockIdx.x;

    // ---- Build fused 4x4 matrices for 2 features (elementwise float2) ----
    float2 lv[4], rv[4];
#pragma unroll
    for (int i = 0; i < 4; i++) {
        lv[i] = *reinterpret_cast<const float2*>(ql + i * QD + d2);
        rv[i] = *reinterpret_cast<const float2*>(qr + i * QD + d2);
    }
    {   // normalize l
        float2 s = make_float2(1e-8f, 1e-8f);
#pragma unroll
        for (int i = 0; i < 4; i++) s = f2_fma(lv[i], lv[i], s);
        float2 inv = make_float2(rsqrtf(s.x), rsqrtf(s.y));
#pragma unroll
        for (int i = 0; i < 4; i++) lv[i] = f2_mul(lv[i], inv);
    }
    {   // normalize r + conjugate
        float2 s = make_float2(1e-8f, 1e-8f);
#pragma unroll
        for (int i = 0; i < 4; i++) s = f2_fma(rv[i], rv[i], s);
        float2 inv = make_float2(rsqrtf(s.x), rsqrtf(s.y));
        rv[0] = f2_mul(rv[0], inv);
        float2 ninv = make_float2(-inv.x, -inv.y);
#pragma unroll
        for (int i = 1; i < 4; i++) rv[i] = f2_mul(rv[i], ninv);
    }

    // Hamilton structure (constant-folded): L[r][k]=sL*l[p[r][k]], R[k][c]=sR*r[p[k][c]]
    const int   pP[4][4] = {{0,1,2,3},{1,0,3,2},{2,3,0,1},{3,2,1,0}};
    const float sL[4][4] = {{1,-1,-1,-1},{1,1,-1,1},{1,1,1,-1},{1,-1,1,1}};
    const float sR[4][4] = {{1,-1,-1,-1},{1,1,1,-1},{1,-1,1,1},{1,1,-1,1}};

    float2 g2 = *reinterpret_cast<const float2*>(gate + d2);

    float2 M[16];
#pragma unroll
    for (int r = 0; r < 4; r++) {
#pragma unroll
        for (int c = 0; c < 4; c++) {
            float2 acc = make_float2(0.f, 0.f);
#pragma unroll
            for (int k = 0; k < 4; k++) {
                float2 t = f2_mul(lv[pP[r][k]], rv[pP[k][c]]);
                if (sL[r][k] * sR[k][c] > 0.f) { acc.x += t.x; acc.y += t.y; }
                else                           { acc.x -= t.x; acc.y -= t.y; }
            }
            M[r * 4 + c] = f2_mul(acc, g2);
        }
    }

    // ---- Persistent loop: two rows per iteration (row, row+NBLK) ----
    const float* xc = x + (size_t)bid * 2048 + d2;
    float* oc = out + (size_t)bid * 2048 + d2;
    int row = bid;

    while (row + NBLK < NBT) {
        // 8 front-batched streaming loads (two rows)
        float2 in0[4], in1[4];
#pragma unroll
        for (int c = 0; c < 4; c++)
            in0[c] = __ldcs(reinterpret_cast<const float2*>(xc + c * QD));
#pragma unroll
        for (int c = 0; c < 4; c++)
            in1[c] = __ldcs(reinterpret_cast<const float2*>(xc + STRIDE + c * QD));

        float2 o0[4], o1[4];
#pragma unroll
        for (int r = 0; r < 4; r++) {
            float2 a = f2_mul(M[r * 4 + 0], in0[0]);
            a = f2_fma(M[r * 4 + 1], in0[1], a);
            a = f2_fma(M[r * 4 + 2], in0[2], a);
            a = f2_fma(M[r * 4 + 3], in0[3], a);
            o0[r] = a;
            float2 b = f2_mul(M[r * 4 + 0], in1[0]);
            b = f2_fma(M[r * 4 + 1], in1[1], b);
            b = f2_fma(M[r * 4 + 2], in1[2], b);
            b = f2_fma(M[r * 4 + 3], in1[3], b);
            o1[r] = b;
        }

        // 8 grouped streaming stores
#pragma unroll
        for (int r = 0; r < 4; r++)
            __stcs(reinterpret_cast<float2*>(oc + r * QD), o0[r]);
#pragma unroll
        for (int r = 0; r < 4; r++)
            __stcs(reinterpret_cast<float2*>(oc + STRIDE + r * QD), o1[r]);

        xc += 2 * STRIDE;
        oc += 2 * STRIDE;
        row += 2 * NBLK;
    }

    // Tail: at most one leftover row
    if (row < NBT) {
        float2 in[4];
#pragma unroll
        for (int c = 0; c < 4; c++)
            in[c] = __ldcs(reinterpret_cast<const float2*>(xc + c * QD));
#pragma unroll
        for (int r = 0; r < 4; r++) {
            float2 a = f2_mul(M[r * 4 + 0], in[0]);
            a = f2_fma(M[r * 4 + 1], in[1], a);
            a = f2_fma(M[r * 4 + 2], in[2], a);
            a = f2_fma(M[r * 4 + 3], in[3], a);
            __stcs(reinterpret_cast<float2*>(oc + r * QD), a);
        }
    }
}

extern "C" void kernel_launch(void* const* d_in, const int* in_sizes, int n_in,
                              void* d_out, int out_size) {
    const float* x    = (const float*)d_in[0];
    const float* ql   = (const float*)d_in[1];
    const float* qr   = (const float*)d_in[2];
    const float* gate = (const float*)d_in[3];
    float* out = (float*)d_out;

    evolve_pair4_kernel<<<NBLK, THREADS>>>(x, ql, qr, gate, out);
}

// round 17
// speedup vs baseline: 1.0155x; 1.0155x over previous
#include <cuda_runtime.h>
#include <cuda_bf16.h>

// D_MODEL = 2048, QUAT_DIM = 512, B*T = 16384
// Inputs: x [B,T,2048] f32, q_left [4,512] f32, q_right [4,512] f32, gate [512] f32
// Output: [B,T,2048] f32
//
// gate broadcasts uniformly over the FFT axis => ifft(fft(x)*g).real == g*x.
// Both Hamilton products are linear in x => fused per-feature 4x4 matrix M[d].
//
// R16: quad-row bursts. Persistent 444-block grid; each iteration front-batches
// 16 streaming loads (4 rows), computes, then issues 16 grouped streaming
// stores. Doubles R12's same-direction DRAM burst length; 16 naked loads per
// thread provide the MLP (no pipeline registers needed).

#define QD 512
#define NBT (4 * 4096)        // 16384 rows
#define THREADS 256
#define NBLK 444              // 148 SMs x 3 grid-resident (occupancy proven non-binding)
#define STRIDE (NBLK * 2048)  // floats between a block's consecutive rows
// 16384 = 444*36 + 400: every block runs 9 quad-iterations;
// blocks 0..399 then process 1 tail row.

__device__ __forceinline__ float2 f2_fma(float2 a, float2 b, float2 c) {
    return make_float2(fmaf(a.x, b.x, c.x), fmaf(a.y, b.y, c.y));
}
__device__ __forceinline__ float2 f2_mul(float2 a, float2 b) {
    return make_float2(a.x * b.x, a.y * b.y);
}

__global__ void __launch_bounds__(THREADS)
evolve_quad_kernel(const float* __restrict__ x,
                   const float* __restrict__ ql,
                   const float* __restrict__ qr,
                   const float* __restrict__ gate,
                   float* __restrict__ out) {
    const int d2 = threadIdx.x * 2;        // feature pair
    const int bid = blockIdx.x;

    // ---- Build fused 4x4 matrices for 2 features (elementwise float2) ----
    float2 lv[4], rv[4];
#pragma unroll
    for (int i = 0; i < 4; i++) {
        lv[i] = *reinterpret_cast<const float2*>(ql + i * QD + d2);
        rv[i] = *reinterpret_cast<const float2*>(qr + i * QD + d2);
    }
    {   // normalize l
        float2 s = make_float2(1e-8f, 1e-8f);
#pragma unroll
        for (int i = 0; i < 4; i++) s = f2_fma(lv[i], lv[i], s);
        float2 inv = make_float2(rsqrtf(s.x), rsqrtf(s.y));
#pragma unroll
        for (int i = 0; i < 4; i++) lv[i] = f2_mul(lv[i], inv);
    }
    {   // normalize r + conjugate
        float2 s = make_float2(1e-8f, 1e-8f);
#pragma unroll
        for (int i = 0; i < 4; i++) s = f2_fma(rv[i], rv[i], s);
        float2 inv = make_float2(rsqrtf(s.x), rsqrtf(s.y));
        rv[0] = f2_mul(rv[0], inv);
        float2 ninv = make_float2(-inv.x, -inv.y);
#pragma unroll
        for (int i = 1; i < 4; i++) rv[i] = f2_mul(rv[i], ninv);
    }

    // Hamilton structure (constant-folded): L[r][k]=sL*l[p[r][k]], R[k][c]=sR*r[p[k][c]]
    const int   pP[4][4] = {{0,1,2,3},{1,0,3,2},{2,3,0,1},{3,2,1,0}};
    const float sL[4][4] = {{1,-1,-1,-1},{1,1,-1,1},{1,1,1,-1},{1,-1,1,1}};
    const float sR[4][4] = {{1,-1,-1,-1},{1,1,1,-1},{1,-1,1,1},{1,1,-1,1}};

    float2 g2 = *reinterpret_cast<const float2*>(gate + d2);

    float2 M[16];
#pragma unroll
    for (int r = 0; r < 4; r++) {
#pragma unroll
        for (int c = 0; c < 4; c++) {
            float2 acc = make_float2(0.f, 0.f);
#pragma unroll
            for (int k = 0; k < 4; k++) {
                float2 t = f2_mul(lv[pP[r][k]], rv[pP[k][c]]);
                if (sL[r][k] * sR[k][c] > 0.f) { acc.x += t.x; acc.y += t.y; }
                else                           { acc.x -= t.x; acc.y -= t.y; }
            }
            M[r * 4 + c] = f2_mul(acc, g2);
        }
    }

    // ---- Persistent loop: four rows per iteration ----
    const float* xc = x + (size_t)bid * 2048 + d2;
    float* oc = out + (size_t)bid * 2048 + d2;
    int row = bid;

    while (row + 3 * NBLK < NBT) {
        // 16 front-batched streaming loads (four rows)
        float2 in[4][4];
#pragma unroll
        for (int j = 0; j < 4; j++)
#pragma unroll
            for (int c = 0; c < 4; c++)
                in[j][c] = __ldcs(reinterpret_cast<const float2*>(
                    xc + (size_t)j * STRIDE + c * QD));

        // Compute all four rows
        float2 o[4][4];
#pragma unroll
        for (int j = 0; j < 4; j++) {
#pragma unroll
            for (int r = 0; r < 4; r++) {
                float2 a = f2_mul(M[r * 4 + 0], in[j][0]);
                a = f2_fma(M[r * 4 + 1], in[j][1], a);
                a = f2_fma(M[r * 4 + 2], in[j][2], a);
                a = f2_fma(M[r * 4 + 3], in[j][3], a);
                o[j][r] = a;
            }
        }

        // 16 grouped streaming stores
#pragma unroll
        for (int j = 0; j < 4; j++)
#pragma unroll
            for (int r = 0; r < 4; r++)
                __stcs(reinterpret_cast<float2*>(
                    oc + (size_t)j * STRIDE + r * QD), o[j][r]);

        xc += 4 * STRIDE;
        oc += 4 * STRIDE;
        row += 4 * NBLK;
    }

    // Tail: up to 3 leftover rows, one at a time
    while (row < NBT) {
        float2 in[4];
#pragma unroll
        for (int c = 0; c < 4; c++)
            in[c] = __ldcs(reinterpret_cast<const float2*>(xc + c * QD));
#pragma unroll
        for (int r = 0; r < 4; r++) {
            float2 a = f2_mul(M[r * 4 + 0], in[0]);
            a = f2_fma(M[r * 4 + 1], in[1], a);
            a = f2_fma(M[r * 4 + 2], in[2], a);
            a = f2_fma(M[r * 4 + 3], in[3], a);
            __stcs(reinterpret_cast<float2*>(oc + r * QD), a);
        }
        xc += STRIDE;
        oc += STRIDE;
        row += NBLK;
    }
}

extern "C" void kernel_launch(void* const* d_in, const int* in_sizes, int n_in,
                              void* d_out, int out_size) {
    const float* x    = (const float*)d_in[0];
    const float* ql   = (const float*)d_in[1];
    const float* qr   = (const float*)d_in[2];
    const float* gate = (const float*)d_in[3];
    float* out = (float*)d_out;

    evolve_quad_kernel<<<NBLK, THREADS>>>(x, ql, qr, gate, out);
}